// round 4
// baseline (speedup 1.0000x reference)
#include <cuda_runtime.h>
#include <math.h>

#define NUM_CLASSES 15
#define NCH 20          // NUM_CLASSES + 5
#define NG 52
#define NA 3
#define PLANE (NG*NG)   // 2704
#define TPB 256
#define SPAD 21         // padded smem stride

__device__ double   g_loss = 0.0;   // reset by last block each call
__device__ unsigned g_done = 0;

// ---------------------------------------------------------------------------
// Fused transform + smem-staged coalesced output + loss reduction + finalize
// One thread per (b, anchor, j, i) cell; block = 256 cells.
// ---------------------------------------------------------------------------
__global__ __launch_bounds__(TPB) void k2_main(
    const float* __restrict__ x, const float* __restrict__ labels,
    float* __restrict__ out, int nB)
{
    __shared__ float sbuf[TPB * SPAD];

    const int tid  = threadIdx.x;
    const int base = blockIdx.x * TPB;
    const int idx  = base + tid;
    const int total = nB * NA * PLANE;
    float loss = 0.0f;

    if (idx < total) {
        int i = idx % NG;
        int j = (idx / NG) % NG;
        int a = (idx / PLANE) % NA;
        int b = idx / (NA * PLANE);

        const float* xb = x + ((size_t)(b * (NA*NCH) + a * NCH)) * PLANE + j * NG + i;

        float ch[NCH];
#pragma unroll
        for (int c = 0; c < NCH; c++)
            ch[c] = __ldcs(xb + (size_t)c * PLANE);   // streaming: no reuse

        // ---- per-thread target meta (broadcast loads, cheap ALU) ----
        float bx = labels[b*5+0] * (float)NG;
        float by = labels[b*5+1] * (float)NG;
        float bw = labels[b*5+2] * (float)NG;
        float bh = labels[b*5+3] * (float)NG;
        int   gcls = (int)labels[b*5+4];
        int   gi = (int)bx;
        int   gj = (int)by;

        const float aw[3] = {12.0f, 9.875f, 10.125f};
        const float ah[3] = {28.75f, 23.25f, 16.625f};
        float iou[3];
#pragma unroll
        for (int k = 0; k < 3; k++) {
            float inter = fminf(aw[k], bw) * fminf(ah[k], bh);
            iou[k] = inter / (aw[k]*ah[k] + 1e-16f + bw*bh - inter);
        }
        int best = 0;
        if (iou[1] > iou[best]) best = 1;
        if (iou[2] > iou[best]) best = 2;

        // ---- elementwise transform ----
        float px   = 1.0f / (1.0f + __expf(-ch[0]));
        float py   = 1.0f / (1.0f + __expf(-ch[1]));
        float pw   = ch[2];
        float ph   = ch[3];
        float conf = 1.0f / (1.0f + __expf(-ch[4]));

        float mx = ch[5];
#pragma unroll
        for (int c = 6; c < NCH; c++) mx = fmaxf(mx, ch[c]);
        float s = 0.0f;
#pragma unroll
        for (int c = 5; c < NCH; c++) { ch[c] = __expf(ch[c] - mx); s += ch[c]; }
        float inv = 1.0f / s;
#pragma unroll
        for (int c = 5; c < NCH; c++) ch[c] *= inv;

        // ---- stage output row in smem ----
        float* srow = &sbuf[tid * SPAD];
        srow[0] = px * 8.0f;
        srow[1] = py * 8.0f;
        srow[2] = pw * 8.0f;
        srow[3] = ph * 8.0f;
        srow[4] = conf;
#pragma unroll
        for (int c = 5; c < NCH; c++) srow[c] = ch[c];

        // ---- loss contributions ----
        bool at_cell = (j == gj) && (i == gi);
        bool is_best = at_cell && (a == best);

        float noobj = 1.0f;
        if (at_cell) {
            if (a == best || iou[a] > 0.5f) noobj = 0.0f;
        }
        if (noobj != 0.0f)
            loss += 100.0f * (-fmaxf(__logf(1.0f - conf), -100.0f));

        if (is_best) {
            float tx = bx - (float)gi;
            float ty = by - (float)gj;
            float tw = __logf(bw / aw[best] + 1e-16f);
            float th = __logf(bh / ah[best] + 1e-16f);
            loss += fabsf(px - tx) + fabsf(py - ty)
                  + fabsf(pw - tw) + fabsf(ph - th);
            loss += -fmaxf(__logf(conf), -100.0f);
#pragma unroll
            for (int c = 0; c < NUM_CLASSES; c++) {
                float p = ch[5 + c];
                if (c == gcls) loss += -fmaxf(__logf(p), -100.0f);
                else           loss += -fmaxf(__logf(1.0f - p), -100.0f);
            }
        }
    }

    __syncthreads();

    // ---- coalesced streaming write: 5120 contiguous floats per block ----
    {
        int ncell = total - base;
        if (ncell > TPB) ncell = TPB;
        int nfl = ncell * NCH;
        size_t gbase = 1 + (size_t)base * NCH;
#pragma unroll
        for (int k = 0; k < NCH; k++) {
            int g = tid + k * TPB;
            if (g < nfl) {
                int cell = g / NCH;
                int c    = g - cell * NCH;
                __stcs(&out[gbase + g], sbuf[cell * SPAD + c]);
            }
        }
    }

    // ---- block reduction -> one double atomic per block ----
    __shared__ float warpsum[TPB / 32];
#pragma unroll
    for (int o = 16; o > 0; o >>= 1)
        loss += __shfl_down_sync(0xffffffffu, loss, o);
    if ((tid & 31) == 0) warpsum[tid >> 5] = loss;
    __syncthreads();

    if (tid == 0) {
        float v = 0.0f;
#pragma unroll
        for (int w = 0; w < TPB / 32; w++) v += warpsum[w];
        atomicAdd(&g_loss, (double)v);
        __threadfence();
        unsigned ticket = atomicAdd(&g_done, 1u);
        if (ticket == gridDim.x - 1) {
            // all blocks' loss atomics are visible (same-address atomic order
            // + threadfence); read total via atomic RMW for coherence.
            double tot = atomicAdd(&g_loss, 0.0);
            out[0] = (float)tot;
            // reset for next graph replay
            atomicExch((unsigned long long*)&g_loss, 0ull);
            atomicExch(&g_done, 0u);
        }
    }
}

extern "C" void kernel_launch(void* const* d_in, const int* in_sizes, int n_in,
                              void* d_out, int out_size) {
    const float* x      = (const float*)d_in[0];
    const float* labels = (const float*)d_in[1];
    float* out = (float*)d_out;

    int nB = in_sizes[0] / (NA * NCH * PLANE);
    int total = nB * NA * PLANE;

    k2_main<<<(total + TPB - 1) / TPB, TPB>>>(x, labels, out, nB);
}